// round 10
// baseline (speedup 1.0000x reference)
#include <cuda_runtime.h>
#include <cuda_bf16.h>
#include <math_constants.h>

#define BATCH 64
#define SEQ   256
#define TCH   16
#define VOC   262
#define EMB   64
#define HID   32
#define G3    96
#define NSEQ  (BATCH*SEQ)

// Tables (device globals — no allocation allowed)
// Permuted GI rows: pos(gate,j) = gate*32 + tig*8 + hg*2 + e
// r,z entries pre-scaled by 0.5 (sigmoid-via-tanh); bhh folded for r,z.
__device__ __align__(128) float g_GI2[2 * VOC * G3];
// Pre-packed bf16 B fragments (m16n8k16): [dir][nb][kc][lane] = uint2(b0,b1)
// nb<8 rows pre-scaled 0.5.
__device__ uint2 g_WF[2 * 12 * 2 * 32];

__device__ __forceinline__ unsigned packbf(float lo, float hi) {
    unsigned d;
    asm("cvt.rn.bf16x2.f32 %0, %1, %2;" : "=r"(d) : "f"(hi), "f"(lo));
    return d;
}
__device__ __forceinline__ float tanhapx(float x) {
    float r;
    asm("tanh.approx.f32 %0, %1;" : "=f"(r) : "f"(x));
    return r;
}
__device__ __forceinline__ void mma_bf16(float* d, const unsigned* a,
                                         unsigned b0, unsigned b1) {
    asm("mma.sync.aligned.m16n8k16.row.col.f32.bf16.bf16.f32 "
        "{%0,%1,%2,%3}, {%4,%5,%6,%7}, {%8,%9}, {%0,%1,%2,%3};"
        : "+f"(d[0]), "+f"(d[1]), "+f"(d[2]), "+f"(d[3])
        : "r"(a[0]), "r"(a[1]), "r"(a[2]), "r"(a[3]),
          "r"(b0), "r"(b1));
}

// ---------------------------------------------------------------------------
// Kernel 1: GI tables + bf16 B-fragment pack. grid = VOC+1, block = 192.
// ---------------------------------------------------------------------------
__global__ void build_tables(const float* __restrict__ emb,
                             const float* __restrict__ Wih_f,
                             const float* __restrict__ bih_f,
                             const float* __restrict__ bhh_f,
                             const float* __restrict__ Wih_b,
                             const float* __restrict__ bih_b,
                             const float* __restrict__ bhh_b,
                             const float* __restrict__ Whh_f,
                             const float* __restrict__ Whh_b) {
    int c   = blockIdx.x;
    int tid = threadIdx.x;
    if (c < VOC) {
        int dir = tid / 96;
        int g   = tid % 96;
        __shared__ float e[EMB];
        if (tid < EMB) e[tid] = emb[c * EMB + tid];
        __syncthreads();
        const float* Wih = dir ? Wih_b : Wih_f;
        const float* bih = dir ? bih_b : bih_f;
        const float* bhh = dir ? bhh_b : bhh_f;
        float a0 = bih[g] + (g < 64 ? bhh[g] : 0.0f);
        float a1 = 0.0f;
        const float4* wr4 = (const float4*)(Wih + g * EMB);
        #pragma unroll
        for (int k4 = 0; k4 < EMB / 4; k4++) {
            float4 wv = wr4[k4];
            a0 = fmaf(wv.x, e[4 * k4],     a0);
            a1 = fmaf(wv.y, e[4 * k4 + 1], a1);
            a0 = fmaf(wv.z, e[4 * k4 + 2], a0);
            a1 = fmaf(wv.w, e[4 * k4 + 3], a1);
        }
        float v = a0 + a1;
        if (g < 64) v *= 0.5f;               // sigmoid-via-tanh prescale
        int gate = g >> 5, j = g & 31;
        int hg = j >> 3, tg = (j >> 1) & 3, eb = j & 1;
        int pos = gate * 32 + tg * 8 + hg * 2 + eb;
        g_GI2[dir * (VOC * G3) + c * G3 + pos] = v;
    } else {
        // pack bf16 B fragments (2*12*2*32 = 1536 uint2)
        for (int i = tid; i < 1536; i += 192) {
            int d    = i / 768;
            int rem  = i % 768;
            int nb   = rem / 64;
            int kc   = (rem / 32) & 1;
            int lane = rem & 31;
            int gid = lane >> 2, tg = lane & 3;
            const float* W = d ? Whh_b : Whh_f;
            const float* row = W + (8 * nb + gid) * HID;
            float s = (nb < 8) ? 0.5f : 1.0f;    // r,z rows prescaled
            int k0 = 16 * kc + 2 * tg;
            g_WF[i] = make_uint2(packbf(s * row[k0],     s * row[k0 + 1]),
                                 packbf(s * row[k0 + 8], s * row[k0 + 9]));
        }
    }
}

// ---------------------------------------------------------------------------
// Kernel 2: bf16 tensor-core GRU, software-pipelined gi loads.
// One warp = 16 sequences, one dir; 2048 warps in 512 blocks x 128 threads
// (4 warps/block) for ~12 resident warps/SM. B fragments in smem (6 KB).
// 24 bf16 m16n8k16 MMAs/step, lane-local D->A conversion.
// ---------------------------------------------------------------------------
__global__ __launch_bounds__(128, 3)
void gru_mma(const int* __restrict__ x,
             const float* __restrict__ bhh_f,
             const float* __restrict__ bhh_b,
             float* __restrict__ out) {
    __shared__ uint2 s_bf[12 * 2 * 32];     // 6 KB B fragments (dir-uniform)

    int tid  = threadIdx.x;
    int wb   = tid >> 5;
    int lane = tid & 31;
    int gid  = lane >> 2;
    int tig  = lane & 3;
    int dir  = blockIdx.x >> 8;                 // block-uniform
    int wi   = (blockIdx.x & 255) * 4 + wb;     // 0..1023
    int seq0 = wi << 4;

    // copy this direction's B fragments to smem (coalesced, once per block)
    {
        const uint2* src = g_WF + dir * 768;
        #pragma unroll
        for (int i = 0; i < 6; i++)
            s_bf[tid + 128 * i] = src[tid + 128 * i];
    }
    __syncthreads();

    const float* __restrict__ GI  = g_GI2 + dir * (VOC * G3);
    const float* __restrict__ bhh = dir ? bhh_b : bhh_f;

    float bn0 = bhh[64 + 2 * tig],      bn0b = bhh[64 + 2 * tig + 1];
    float bn1 = bhh[64 + 8 + 2 * tig],  bn1b = bhh[64 + 8 + 2 * tig + 1];
    float bn2 = bhh[64 + 16 + 2 * tig], bn2b = bhh[64 + 16 + 2 * tig + 1];
    float bn3 = bhh[64 + 24 + 2 * tig], bn3b = bhh[64 + 24 + 2 * tig + 1];

    const int* xA = x + (seq0 + gid) * TCH;
    const int* xB = x + (seq0 + gid + 8) * TCH;

    float hn[4][4], hmax[4][4];
    #pragma unroll
    for (int hg = 0; hg < 4; hg++)
        #pragma unroll
        for (int s = 0; s < 4; s++) { hn[hg][s] = 0.0f; hmax[hg][s] = -CUDART_INF_F; }

    int t0 = dir ? (TCH - 1) : 0;
    int t1 = dir ? (TCH - 2) : 1;
    int cA = xA[t0], cB = xB[t0];

    // gi for step 0 (current buffer)
    const float4* gA4 = (const float4*)(GI + cA * G3);
    const float4* gB4 = (const float4*)(GI + cB * G3);
    float4 ra0 = gA4[tig * 2],      ra1 = gA4[tig * 2 + 1];
    float4 za0 = gA4[8 + tig * 2],  za1 = gA4[8 + tig * 2 + 1];
    float4 na0 = gA4[16 + tig * 2], na1 = gA4[16 + tig * 2 + 1];
    float4 rb0 = gB4[tig * 2],      rb1 = gB4[tig * 2 + 1];
    float4 zb0 = gB4[8 + tig * 2],  zb1 = gB4[8 + tig * 2 + 1];
    float4 nb0 = gB4[16 + tig * 2], nb1 = gB4[16 + tig * 2 + 1];

    // char indices for step 1
    int cAn = xA[t1], cBn = xB[t1];

    #pragma unroll 1
    for (int tt = 0; tt < TCH; ++tt) {
        // --- prefetch: gi for step tt+1 (addresses ready in cAn/cBn) ---
        const float4* pA4 = (const float4*)(GI + cAn * G3);
        const float4* pB4 = (const float4*)(GI + cBn * G3);
        float4 pra0 = pA4[tig * 2],      pra1 = pA4[tig * 2 + 1];
        float4 pza0 = pA4[8 + tig * 2],  pza1 = pA4[8 + tig * 2 + 1];
        float4 pna0 = pA4[16 + tig * 2], pna1 = pA4[16 + tig * 2 + 1];
        float4 prb0 = pB4[tig * 2],      prb1 = pB4[tig * 2 + 1];
        float4 pzb0 = pB4[8 + tig * 2],  pzb1 = pB4[8 + tig * 2 + 1];
        float4 pnb0 = pB4[16 + tig * 2], pnb1 = pB4[16 + tig * 2 + 1];

        // --- prefetch: char indices for step tt+2 ---
        int tn2 = dir ? ((TCH - 3 - tt) & (TCH - 1)) : ((tt + 2) & (TCH - 1));
        cAn = xA[tn2];
        cBn = xB[tn2];

        // --- compute step tt from current registers ---
        unsigned a[2][4];
        #pragma unroll
        for (int kc = 0; kc < 2; kc++) {
            a[kc][0] = packbf(hn[2 * kc][0],     hn[2 * kc][1]);
            a[kc][1] = packbf(hn[2 * kc][2],     hn[2 * kc][3]);
            a[kc][2] = packbf(hn[2 * kc + 1][0], hn[2 * kc + 1][1]);
            a[kc][3] = packbf(hn[2 * kc + 1][2], hn[2 * kc + 1][3]);
        }

        float acc[12][4];
        acc[0][0]=ra0.x;  acc[0][1]=ra0.y;  acc[1][0]=ra0.z;  acc[1][1]=ra0.w;
        acc[2][0]=ra1.x;  acc[2][1]=ra1.y;  acc[3][0]=ra1.z;  acc[3][1]=ra1.w;
        acc[0][2]=rb0.x;  acc[0][3]=rb0.y;  acc[1][2]=rb0.z;  acc[1][3]=rb0.w;
        acc[2][2]=rb1.x;  acc[2][3]=rb1.y;  acc[3][2]=rb1.z;  acc[3][3]=rb1.w;
        acc[4][0]=za0.x;  acc[4][1]=za0.y;  acc[5][0]=za0.z;  acc[5][1]=za0.w;
        acc[6][0]=za1.x;  acc[6][1]=za1.y;  acc[7][0]=za1.z;  acc[7][1]=za1.w;
        acc[4][2]=zb0.x;  acc[4][3]=zb0.y;  acc[5][2]=zb0.z;  acc[5][3]=zb0.w;
        acc[6][2]=zb1.x;  acc[6][3]=zb1.y;  acc[7][2]=zb1.z;  acc[7][3]=zb1.w;
        acc[8][0]=bn0;  acc[8][1]=bn0b;  acc[9][0]=bn1;  acc[9][1]=bn1b;
        acc[10][0]=bn2; acc[10][1]=bn2b; acc[11][0]=bn3; acc[11][1]=bn3b;
        acc[8][2]=bn0;  acc[8][3]=bn0b;  acc[9][2]=bn1;  acc[9][3]=bn1b;
        acc[10][2]=bn2; acc[10][3]=bn2b; acc[11][2]=bn3; acc[11][3]=bn3b;

        float gin[4][4];
        gin[0][0]=na0.x; gin[0][1]=na0.y; gin[1][0]=na0.z; gin[1][1]=na0.w;
        gin[2][0]=na1.x; gin[2][1]=na1.y; gin[3][0]=na1.z; gin[3][1]=na1.w;
        gin[0][2]=nb0.x; gin[0][3]=nb0.y; gin[1][2]=nb0.z; gin[1][3]=nb0.w;
        gin[2][2]=nb1.x; gin[2][3]=nb1.y; gin[3][2]=nb1.z; gin[3][3]=nb1.w;

        #pragma unroll
        for (int kc = 0; kc < 2; kc++)
            #pragma unroll
            for (int nb = 0; nb < 12; nb++) {
                uint2 b = s_bf[(nb * 2 + kc) * 32 + lane];
                mma_bf16(acc[nb], a[kc], b.x, b.y);
            }

        #pragma unroll
        for (int hg = 0; hg < 4; hg++)
            #pragma unroll
            for (int s = 0; s < 4; s++) {
                float r = fmaf(tanhapx(acc[hg][s]),     0.5f, 0.5f);
                float z = fmaf(tanhapx(acc[4 + hg][s]), 0.5f, 0.5f);
                float n = tanhapx(fmaf(r, acc[8 + hg][s], gin[hg][s]));
                float h = fmaf(z, hn[hg][s] - n, n);
                hn[hg][s] = h;
                hmax[hg][s] = fmaxf(hmax[hg][s], h);
            }

        // rotate prefetch buffer into current
        ra0 = pra0; ra1 = pra1; za0 = pza0; za1 = pza1; na0 = pna0; na1 = pna1;
        rb0 = prb0; rb1 = prb1; zb0 = pzb0; zb1 = pzb1; nb0 = pnb0; nb1 = pnb1;
    }

    int sA = seq0 + gid, sB = seq0 + gid + 8;
    #pragma unroll
    for (int hg = 0; hg < 4; hg++) {
        int col = 8 * hg + 2 * tig;
        *(float2*)(out + sA * 64 + dir * 32 + col) = make_float2(hmax[hg][0], hmax[hg][1]);
        *(float2*)(out + sB * 64 + dir * 32 + col) = make_float2(hmax[hg][2], hmax[hg][3]);
    }
}

// ---------------------------------------------------------------------------
// kernel_launch
// ---------------------------------------------------------------------------
extern "C" void kernel_launch(void* const* d_in, const int* in_sizes, int n_in,
                              void* d_out, int out_size) {
    const int*   x     = (const int*)  d_in[0];
    const float* emb   = (const float*)d_in[1];
    const float* Wih_f = (const float*)d_in[2];
    const float* Whh_f = (const float*)d_in[3];
    const float* bih_f = (const float*)d_in[4];
    const float* bhh_f = (const float*)d_in[5];
    const float* Wih_b = (const float*)d_in[6];
    const float* Whh_b = (const float*)d_in[7];
    const float* bih_b = (const float*)d_in[8];
    const float* bhh_b = (const float*)d_in[9];
    float* out = (float*)d_out;

    build_tables<<<VOC + 1, 192>>>(emb, Wih_f, bih_f, bhh_f,
                                   Wih_b, bih_b, bhh_b, Whh_f, Whh_b);

    // 512 blocks x 4 warps = 2048 warps; one 16-seq task per warp.
    // Blocks 0..255 dir0, 256..511 dir1.
    gru_mma<<<512, 128>>>(x, bhh_f, bhh_b, out);
}